// round 4
// baseline (speedup 1.0000x reference)
#include <cuda_runtime.h>
#include <stdint.h>
#include <stddef.h>

// ---------------------------------------------------------------------------
// JAX PRNG variant switch:
//   1 = "partitionable" threefry (default in modern JAX)
//   0 = original/legacy threefry counter layout
#define JAX_PARTITIONABLE 1
// ---------------------------------------------------------------------------

#define NROWS_MAX 100000
#define NEDGE_MAX 1200000

struct U2 { uint32_t x, y; };
struct __align__(8) Edge { int col; float val; };

// ------------------------------ threefry2x32 -------------------------------
static __host__ __device__ __forceinline__ uint32_t rotl32(uint32_t x, uint32_t r) {
#ifdef __CUDA_ARCH__
    return __funnelshift_l(x, x, r);
#else
    return (x << r) | (x >> (32u - r));
#endif
}

static __host__ __device__ __forceinline__ U2 threefry2x32(uint32_t k0, uint32_t k1,
                                                           uint32_t x0, uint32_t x1) {
    uint32_t k2 = k0 ^ k1 ^ 0x1BD11BDAu;
    x0 += k0; x1 += k1;
#define TF_R(r) { x0 += x1; x1 = rotl32(x1, r); x1 ^= x0; }
    TF_R(13) TF_R(15) TF_R(26) TF_R(6)   x0 += k1; x1 += k2 + 1u;
    TF_R(17) TF_R(29) TF_R(16) TF_R(24)  x0 += k2; x1 += k0 + 2u;
    TF_R(13) TF_R(15) TF_R(26) TF_R(6)   x0 += k0; x1 += k1 + 3u;
    TF_R(17) TF_R(29) TF_R(16) TF_R(24)  x0 += k1; x1 += k2 + 4u;
    TF_R(13) TF_R(15) TF_R(26) TF_R(6)   x0 += k2; x1 += k0 + 5u;
#undef TF_R
    U2 r; r.x = x0; r.y = x1; return r;
}

// keep (u < 0.9) for element idx of a mask of even total size (half = size/2)
static __device__ __forceinline__ bool keep_90(uint32_t k0, uint32_t k1,
                                               uint32_t idx, uint32_t half) {
#if JAX_PARTITIONABLE
    (void)half;
    U2 o = threefry2x32(k0, k1, 0u, idx);
    uint32_t bits = o.x ^ o.y;
#else
    uint32_t bits;
    if (idx < half) { U2 o = threefry2x32(k0, k1, idx, idx + half); bits = o.x; }
    else            { U2 o = threefry2x32(k0, k1, idx - half, idx); bits = o.y; }
#endif
    float u = __uint_as_float(0x3f800000u | (bits >> 9)) - 1.0f;
    return u < 0.9f;
}

// ------------------------------ device scratch -----------------------------
__device__ int   g_cnt[NROWS_MAX];
__device__ int   g_rowptr[NROWS_MAX];
__device__ int   g_rowend[NROWS_MAX];
__device__ int   g_cursor[NROWS_MAX];
__device__ int   g_blk[256];
__device__ int   g_eid[NEDGE_MAX];
__device__ Edge  g_edges[NEDGE_MAX];
__device__ float g_egoA[(size_t)NROWS_MAX * 64];
__device__ float g_egoB[(size_t)NROWS_MAX * 64];

// ------------------------------ small kernels ------------------------------
__global__ void k_zero(int n) {
    int i = blockIdx.x * blockDim.x + threadIdx.x;
    if (i < n) g_cnt[i] = 0;
}

__global__ void k_hist(const int* __restrict__ rows, int E,
                       uint32_t k0, uint32_t k1, uint32_t half) {
    int e = blockIdx.x * blockDim.x + threadIdx.x;
    if (e >= E) return;
    if (keep_90(k0, k1, (uint32_t)e, half)) atomicAdd(&g_cnt[rows[e]], 1);
}

__global__ void k_scan1(int n) {
    __shared__ int s[1024];
    int i = blockIdx.x * 1024 + threadIdx.x;
    int c = (i < n) ? g_cnt[i] : 0;
    s[threadIdx.x] = c;
    __syncthreads();
    for (int off = 1; off < 1024; off <<= 1) {
        int v = (threadIdx.x >= (unsigned)off) ? s[threadIdx.x - off] : 0;
        __syncthreads();
        s[threadIdx.x] += v;
        __syncthreads();
    }
    if (i < n) g_rowptr[i] = s[threadIdx.x] - c;   // exclusive within block
    if (threadIdx.x == 1023) g_blk[blockIdx.x] = s[1023];
}

__global__ void k_scan2(int nb) {
    if (blockIdx.x == 0 && threadIdx.x == 0) {
        int run = 0;
        for (int b = 0; b < nb; b++) { int t = g_blk[b]; g_blk[b] = run; run += t; }
    }
}

__global__ void k_scan3(int n) {
    int i = blockIdx.x * blockDim.x + threadIdx.x;
    if (i >= n) return;
    int v = g_rowptr[i] + g_blk[i >> 10];
    g_rowptr[i] = v;
    g_cursor[i] = v;
    g_rowend[i] = v + g_cnt[i];
}

__global__ void k_scatter(const int* __restrict__ rows, int E,
                          uint32_t k0, uint32_t k1, uint32_t half) {
    int e = blockIdx.x * blockDim.x + threadIdx.x;
    if (e >= E) return;
    if (keep_90(k0, k1, (uint32_t)e, half)) {
        int p = atomicAdd(&g_cursor[rows[e]], 1);
        g_eid[p] = e;
    }
}

// deterministic ordering: sort each row's edge ids ascending, then materialize
__global__ void k_sortfill(const int* __restrict__ cols, const float* __restrict__ vals, int n) {
    int r = blockIdx.x * blockDim.x + threadIdx.x;
    if (r >= n) return;
    int s = g_rowptr[r], t = g_rowend[r];
    for (int i = s + 1; i < t; i++) {
        int key = g_eid[i];
        int j = i - 1;
        while (j >= s && g_eid[j] > key) { g_eid[j + 1] = g_eid[j]; j--; }
        g_eid[j + 1] = key;
    }
    for (int i = s; i < t; i++) {
        int e = g_eid[i];
        Edge ed; ed.col = cols[e]; ed.val = vals[e] * (1.0f / 0.9f);
        g_edges[i] = ed;
    }
}

// ------------------------------ fused layer kernel -------------------------
__device__ __forceinline__ void fma4(float4& a, float v, const float4& x) {
    a.x = fmaf(v, x.x, a.x); a.y = fmaf(v, x.y, a.y);
    a.z = fmaf(v, x.z, a.z); a.w = fmaf(v, x.w, a.w);
}

#define LB_THREADS 256
#define LB_ROWS    64   // rows per block; 4 threads per row in SpMM phase

__global__ void __launch_bounds__(LB_THREADS)
k_layer(int srcSel,                       // 0 = emb param, 1 = egoA, 2 = egoB
        const float4* __restrict__ embIn, // emb (float4 view)
        int dstSel,                       // 1 = egoA, 2 = egoB
        const float* __restrict__ W, const float* __restrict__ b,
        float4* __restrict__ out4,        // out as float4, row stride 64
        int layer,                        // output column block = layer+1
        uint32_t k0, uint32_t k1, uint32_t half,
        int copyEmb, int n)
{
    __shared__ __align__(16) float4 Ws[64 * 16];
    __shared__ __align__(16) float  side[LB_ROWS][68];   // padded rows (17 float4)
    __shared__ __align__(16) float  bs[64];

    const float4* ego = (srcSel == 0) ? embIn
                       : (srcSel == 1) ? (const float4*)g_egoA : (const float4*)g_egoB;
    float4* egoOut = (dstSel == 1) ? (float4*)g_egoA : (float4*)g_egoB;

    int tid = threadIdx.x;
    const float4* W4 = (const float4*)W;
    for (int i = tid; i < 1024; i += LB_THREADS) Ws[i] = W4[i];
    if (tid < 16) ((float4*)bs)[tid] = ((const float4*)b)[tid];

    // -------- SpMM phase: 4 threads per row, each owns 4 float4 slots ------
    int lr = tid >> 2;        // 0..63 local row
    int l4 = tid & 3;         // 0..3  quarter
    int r  = blockIdx.x * LB_ROWS + lr;
    bool valid = (r < n);

    float4 a0 = {0,0,0,0}, a1 = a0, a2 = a0, a3 = a0;
    if (valid) {
        int e   = g_rowptr[r];
        int end = g_rowend[r];
        for (; e + 1 < end; e += 2) {
            Edge e0 = g_edges[e];
            Edge e1 = g_edges[e + 1];
            const float4* p0 = ego + ((size_t)e0.col << 4) + l4;
            const float4* p1 = ego + ((size_t)e1.col << 4) + l4;
            float4 x00 = __ldg(p0),     x01 = __ldg(p0 + 4),
                   x02 = __ldg(p0 + 8), x03 = __ldg(p0 + 12);
            float4 x10 = __ldg(p1),     x11 = __ldg(p1 + 4),
                   x12 = __ldg(p1 + 8), x13 = __ldg(p1 + 12);
            fma4(a0, e0.val, x00); fma4(a1, e0.val, x01);
            fma4(a2, e0.val, x02); fma4(a3, e0.val, x03);
            fma4(a0, e1.val, x10); fma4(a1, e1.val, x11);
            fma4(a2, e1.val, x12); fma4(a3, e1.val, x13);
        }
        if (e < end) {
            Edge e0 = g_edges[e];
            const float4* p0 = ego + ((size_t)e0.col << 4) + l4;
            fma4(a0, e0.val, __ldg(p0));     fma4(a1, e0.val, __ldg(p0 + 4));
            fma4(a2, e0.val, __ldg(p0 + 8)); fma4(a3, e0.val, __ldg(p0 + 12));
        }
    }
    {
        float4* sp = (float4*)(&side[lr][0]);
        sp[l4] = a0; sp[l4 + 4] = a1; sp[l4 + 8] = a2; sp[l4 + 12] = a3;
    }
    __syncthreads();

    // -------- GEMM phase: thread = 4 cols (cg) x 4 rows (rq) ----------------
    int cg = tid & 15;        // column group: cols cg*4 .. cg*4+3
    int rq = tid >> 4;        // row quad:     rows rq*4 .. rq*4+3 (local)
    int rbase = blockIdx.x * LB_ROWS + rq * 4;

    float4 h[4];
    float4 bb = ((const float4*)bs)[cg];
    #pragma unroll
    for (int m = 0; m < 4; m++) h[m] = bb;

    #pragma unroll 16
    for (int k = 0; k < 64; k++) {
        float4 w = Ws[k * 16 + cg];
        #pragma unroll
        for (int m = 0; m < 4; m++) {
            float s = side[rq * 4 + m][k];
            h[m].x = fmaf(s, w.x, h[m].x);
            h[m].y = fmaf(s, w.y, h[m].y);
            h[m].z = fmaf(s, w.z, h[m].z);
            h[m].w = fmaf(s, w.w, h[m].w);
        }
    }

    // -------- dropout + write ego_next + row-normalize + write out ----------
    #pragma unroll
    for (int m = 0; m < 4; m++) {
        int row = rbase + m;
        uint32_t base = (uint32_t)row * 64u + (uint32_t)cg * 4u;
        float4 hm = h[m];
        hm.x = keep_90(k0, k1, base + 0u, half) ? hm.x * (1.0f / 0.9f) : 0.0f;
        hm.y = keep_90(k0, k1, base + 1u, half) ? hm.y * (1.0f / 0.9f) : 0.0f;
        hm.z = keep_90(k0, k1, base + 2u, half) ? hm.z * (1.0f / 0.9f) : 0.0f;
        hm.w = keep_90(k0, k1, base + 3u, half) ? hm.w * (1.0f / 0.9f) : 0.0f;

        float ss = hm.x * hm.x + hm.y * hm.y + hm.z * hm.z + hm.w * hm.w;
        // reduce across the 16 contiguous lanes sharing this rq
        #pragma unroll
        for (int msk = 1; msk <= 8; msk <<= 1)
            ss += __shfl_xor_sync(0xffffffffu, ss, msk);

        float nrm  = sqrtf(ss);
        float invn = 1.0f / fmaxf(nrm, 1e-12f);

        if (row < n) {
            egoOut[(size_t)row * 16 + cg] = hm;
            float4 o;
            o.x = hm.x * invn; o.y = hm.y * invn;
            o.z = hm.z * invn; o.w = hm.w * invn;
            out4[(size_t)row * 64 + (size_t)(layer + 1) * 16 + cg] = o;
            if (copyEmb)
                out4[(size_t)row * 64 + cg] = embIn[(size_t)row * 16 + cg];
        }
    }
}

// ------------------------------ host entry ---------------------------------
extern "C" void kernel_launch(void* const* d_in, const int* in_sizes, int n_in,
                              void* d_out, int out_size) {
    const int*   rows = (const int*)d_in[0];
    const int*   cols = (const int*)d_in[1];
    const float* vals = (const float*)d_in[2];
    const float* emb  = (const float*)d_in[3];
    const float* W0   = (const float*)d_in[4];
    const float* b0   = (const float*)d_in[5];
    const float* W1   = (const float*)d_in[6];
    const float* b1   = (const float*)d_in[7];
    const float* W2   = (const float*)d_in[8];
    const float* b2   = (const float*)d_in[9];

    int E = in_sizes[0];
    int N = in_sizes[3] / 64;
    if (E > NEDGE_MAX) E = NEDGE_MAX;
    if (N > NROWS_MAX) N = NROWS_MAX;
    float* out = (float*)d_out;

    // derive subkeys of jax.random.key(42) -> split(.,4): [k_node, k0, k1, k2]
    U2 kn, kA, kB, kC;
#if JAX_PARTITIONABLE
    kn = threefry2x32(0u, 42u, 0u, 0u);
    kA = threefry2x32(0u, 42u, 0u, 1u);
    kB = threefry2x32(0u, 42u, 0u, 2u);
    kC = threefry2x32(0u, 42u, 0u, 3u);
#else
    U2 p0 = threefry2x32(0u, 42u, 0u, 4u);
    U2 p1 = threefry2x32(0u, 42u, 1u, 5u);
    U2 p2 = threefry2x32(0u, 42u, 2u, 6u);
    U2 p3 = threefry2x32(0u, 42u, 3u, 7u);
    kn.x = p0.x; kn.y = p1.x;
    kA.x = p2.x; kA.y = p3.x;
    kB.x = p0.y; kB.y = p1.y;
    kC.x = p2.y; kC.y = p3.y;
#endif

    uint32_t halfE = (uint32_t)(E / 2);
    uint32_t halfM = (uint32_t)(((long long)N * 64) / 2);

    int tb = 256;
    k_zero   <<<(N + tb - 1) / tb, tb>>>(N);
    k_hist   <<<(E + tb - 1) / tb, tb>>>(rows, E, kn.x, kn.y, halfE);
    int nb = (N + 1023) / 1024;
    k_scan1  <<<nb, 1024>>>(N);
    k_scan2  <<<1, 32>>>(nb);
    k_scan3  <<<(N + tb - 1) / tb, tb>>>(N);
    k_scatter<<<(E + tb - 1) / tb, tb>>>(rows, E, kn.x, kn.y, halfE);
    k_sortfill<<<(N + tb - 1) / tb, tb>>>(cols, vals, N);

    int gb = (N + LB_ROWS - 1) / LB_ROWS;
    // layer 0: ego = emb,  dst = egoA, also copy emb into out block 0
    k_layer<<<gb, LB_THREADS>>>(0, (const float4*)emb, 1, W0, b0,
                                (float4*)out, 0, kA.x, kA.y, halfM, 1, N);
    // layer 1: ego = egoA, dst = egoB
    k_layer<<<gb, LB_THREADS>>>(1, (const float4*)emb, 2, W1, b1,
                                (float4*)out, 1, kB.x, kB.y, halfM, 0, N);
    // layer 2: ego = egoB, dst = egoA
    k_layer<<<gb, LB_THREADS>>>(2, (const float4*)emb, 1, W2, b2,
                                (float4*)out, 2, kC.x, kC.y, halfM, 0, N);
}